// round 4
// baseline (speedup 1.0000x reference)
#include <cuda_runtime.h>
#include <math.h>

#define HID 64
#define BD 128
#define NMAX 262144

// Scratch (no allocation allowed) ------------------------------------------
__device__ float g_dt[NMAX];   // dT/dt per phys point
__device__ float g_xx[NMAX];   // d2T/dx2 per phys point
__device__ double g_sums[2];   // [0] = sum (pred-y)^2, [1] = sum residual^2

__global__ void k_zero() { g_sums[0] = 0.0; g_sums[1] = 0.0; }

// Fast, branch-free, accurate-enough tanh (abs err ~1e-6).
__device__ __forceinline__ float my_tanhf(float z) {
    float zc = fminf(fmaxf(z, -15.f), 15.f);
    float e  = __expf(2.f * zc);
    return 1.f - __fdividef(2.f, e + 1.f);
}

// Activation + forward-mode derivative propagation through tanh.
// h = tanh(z); s = 1 - h^2; u_out = s*zu; w_out = s*zw - 2*h*s*zu^2.
template <int NQ>
__device__ __forceinline__ void act_store(float* sh_h, float* sh_u, float* sh_w,
                                          int idx, float zh, float zu, float zw) {
    float t = my_tanhf(zh);
    float s = 1.f - t * t;
    sh_h[idx] = t;
    if constexpr (NQ >= 2) sh_u[idx] = s * zu;
    if constexpr (NQ == 3) sh_w[idx] = s * zw - 2.f * t * s * zu * zu;
}

__device__ __forceinline__ void block_reduce_atomic(double v, double* slot, float* shbase) {
    #pragma unroll
    for (int off = 16; off; off >>= 1)
        v += __shfl_down_sync(0xffffffffu, v, off);
    __syncthreads();                       // state reads done before scratch reuse
    double* red = (double*)shbase;
    int lane = threadIdx.x & 31, wid = threadIdx.x >> 5;
    if (lane == 0) red[wid] = v;
    __syncthreads();
    if (threadIdx.x == 0) {
        double s = 0.0;
        #pragma unroll
        for (int w = 0; w < BD / 32; w++) s += red[w];
        atomicAdd(slot, s);
    }
}

// NQ: #propagated quantities (1=value, 2=value+grad, 3=value+grad+2nd deriv)
// TD: tangent input dimension (0=x, 1=y, 2=t)
// MODE: 0 = data loss accumulate; 1 = write g_dt; 2 = write g_xx;
//       3 = compute w_yy, fuse PDE residual, accumulate pde loss
template <int NQ, int TD, int MODE>
__global__ __launch_bounds__(BD) void k_pass(
    const float* __restrict__ xin,
    const float* __restrict__ ydata,
    const float* __restrict__ W0, const float* __restrict__ b0,
    const float* __restrict__ W1, const float* __restrict__ b1,
    const float* __restrict__ W2, const float* __restrict__ b2,
    const float* __restrict__ W3, const float* __restrict__ b3,
    const float* __restrict__ W4, const float* __restrict__ b4,
    const float* __restrict__ log_alpha,
    int n)
{
    extern __shared__ float sh[];
    float* sh_h = sh;                       // [HID][BD] per-thread columns
    float* sh_u = sh + HID * BD;
    float* sh_w = sh + 2 * HID * BD;
    const int tid = threadIdx.x;
    const int p   = blockIdx.x * BD + tid;
    const bool active = p < n;

    float x0 = 0.f, x1 = 0.f, x2 = 0.f;
    if (active) { x0 = xin[3 * p]; x1 = xin[3 * p + 1]; x2 = xin[3 * p + 2]; }

    // ---- layer 0: 3 -> 64 (tangent = e_TD, second-order tangent = 0) ----
    #pragma unroll 16
    for (int j = 0; j < HID; j++) {
        float zh = __ldg(b0 + j) + x0 * __ldg(W0 + j)
                                 + x1 * __ldg(W0 + HID + j)
                                 + x2 * __ldg(W0 + 2 * HID + j);
        float zu = 0.f;
        if constexpr (NQ >= 2) zu = __ldg(W0 + TD * HID + j);
        act_store<NQ>(sh_h, sh_u, sh_w, j * BD + tid, zh, zu, 0.f);
    }

    // ---- hidden layers 1..3: 64 -> 64 ----
    const float* Wl[3]  = {W1, W2, W3};
    const float* blp[3] = {b1, b2, b3};
    for (int l = 0; l < 3; l++) {
        float zh[HID];
        float zu[(NQ >= 2) ? HID : 1];
        float zw[(NQ == 3) ? HID : 1];
        const float* bb = blp[l];
        #pragma unroll
        for (int j = 0; j < HID; j++) {
            zh[j] = __ldg(bb + j);
            if constexpr (NQ >= 2) zu[j] = 0.f;
            if constexpr (NQ == 3) zw[j] = 0.f;
        }
        const float* W = Wl[l];
        for (int i = 0; i < HID; i++) {     // rolled: small code, regs for z only
            float hv = sh_h[i * BD + tid];
            float uv = 0.f, wv = 0.f;
            if constexpr (NQ >= 2) uv = sh_u[i * BD + tid];
            if constexpr (NQ == 3) wv = sh_w[i * BD + tid];
            const float4* Wr = (const float4*)(W + i * HID);
            #pragma unroll
            for (int jj = 0; jj < HID / 4; jj++) {
                float4 w4 = __ldg(Wr + jj);
                zh[4*jj+0] += hv * w4.x; zh[4*jj+1] += hv * w4.y;
                zh[4*jj+2] += hv * w4.z; zh[4*jj+3] += hv * w4.w;
                if constexpr (NQ >= 2) {
                    zu[4*jj+0] += uv * w4.x; zu[4*jj+1] += uv * w4.y;
                    zu[4*jj+2] += uv * w4.z; zu[4*jj+3] += uv * w4.w;
                }
                if constexpr (NQ == 3) {
                    zw[4*jj+0] += wv * w4.x; zw[4*jj+1] += wv * w4.y;
                    zw[4*jj+2] += wv * w4.z; zw[4*jj+3] += wv * w4.w;
                }
            }
        }
        #pragma unroll
        for (int j = 0; j < HID; j++) {
            act_store<NQ>(sh_h, sh_u, sh_w, j * BD + tid, zh[j],
                          (NQ >= 2) ? zu[j] : 0.f, (NQ == 3) ? zw[j] : 0.f);
        }
    }

    // ---- output layer: 64 -> 1 (linear) ----
    float ah = __ldg(b4), au = 0.f, aw = 0.f;
    for (int i = 0; i < HID; i++) {
        float wt = __ldg(W4 + i);
        ah += sh_h[i * BD + tid] * wt;
        if constexpr (NQ >= 2) au += sh_u[i * BD + tid] * wt;
        if constexpr (NQ == 3) aw += sh_w[i * BD + tid] * wt;
    }

    if constexpr (MODE == 0) {
        double local = 0.0;
        if (active) { float d = ah - ydata[p]; local = (double)d * (double)d; }
        block_reduce_atomic(local, &g_sums[0], sh);
    } else if constexpr (MODE == 1) {
        if (active) g_dt[p] = au;
    } else if constexpr (MODE == 2) {
        if (active) g_xx[p] = aw;
    } else {  // MODE == 3: fuse PDE residual
        double local = 0.0;
        if (active) {
            float alpha = expf(__ldg(log_alpha));
            float r = g_dt[p] - alpha * (g_xx[p] + aw);
            local = (double)r * (double)r;
        }
        block_reduce_atomic(local, &g_sums[1], sh);
    }
}

__global__ void k_final(const float* __restrict__ log_lambda,
                        const float* __restrict__ log_alpha,
                        float* __restrict__ out, int n)
{
    float data_loss = (float)(g_sums[0] / (double)n);
    float pde_loss  = (float)(g_sums[1] / (double)n);
    float alpha = expf(log_alpha[0]);
    float lam   = expf(log_lambda[0]);
    out[0] = data_loss + lam * pde_loss;
    out[1] = data_loss;
    out[2] = pde_loss;
    out[3] = alpha;
    out[4] = lam;
}

extern "C" void kernel_launch(void* const* d_in, const int* in_sizes, int n_in,
                              void* d_out, int out_size)
{
    const float* x_data     = (const float*)d_in[0];
    const float* y_data     = (const float*)d_in[1];
    const float* x_phys     = (const float*)d_in[2];
    const float* W0 = (const float*)d_in[3];  const float* b0 = (const float*)d_in[4];
    const float* W1 = (const float*)d_in[5];  const float* b1 = (const float*)d_in[6];
    const float* W2 = (const float*)d_in[7];  const float* b2 = (const float*)d_in[8];
    const float* W3 = (const float*)d_in[9];  const float* b3 = (const float*)d_in[10];
    const float* W4 = (const float*)d_in[11]; const float* b4 = (const float*)d_in[12];
    const float* log_lambda = (const float*)d_in[13];
    const float* log_alpha  = (const float*)d_in[14];
    float* out = (float*)d_out;

    int n = in_sizes[0] / 3;
    int grid = (n + BD - 1) / BD;

    const int SH1 = 1 * HID * BD * (int)sizeof(float);  // 32 KB
    const int SH2 = 2 * HID * BD * (int)sizeof(float);  // 64 KB
    const int SH3 = 3 * HID * BD * (int)sizeof(float);  // 96 KB

    cudaFuncSetAttribute(k_pass<1, 0, 0>, cudaFuncAttributeMaxDynamicSharedMemorySize, SH1);
    cudaFuncSetAttribute(k_pass<2, 2, 1>, cudaFuncAttributeMaxDynamicSharedMemorySize, SH2);
    cudaFuncSetAttribute(k_pass<3, 0, 2>, cudaFuncAttributeMaxDynamicSharedMemorySize, SH3);
    cudaFuncSetAttribute(k_pass<3, 1, 3>, cudaFuncAttributeMaxDynamicSharedMemorySize, SH3);

    k_zero<<<1, 1>>>();
    // data loss at x_data
    k_pass<1, 0, 0><<<grid, BD, SH1>>>(x_data, y_data, W0, b0, W1, b1, W2, b2,
                                       W3, b3, W4, b4, log_alpha, n);
    // dT/dt at x_phys
    k_pass<2, 2, 1><<<grid, BD, SH2>>>(x_phys, nullptr, W0, b0, W1, b1, W2, b2,
                                       W3, b3, W4, b4, log_alpha, n);
    // d2T/dx2 at x_phys
    k_pass<3, 0, 2><<<grid, BD, SH3>>>(x_phys, nullptr, W0, b0, W1, b1, W2, b2,
                                       W3, b3, W4, b4, log_alpha, n);
    // d2T/dy2 at x_phys + fused PDE residual accumulation
    k_pass<3, 1, 3><<<grid, BD, SH3>>>(x_phys, nullptr, W0, b0, W1, b1, W2, b2,
                                       W3, b3, W4, b4, log_alpha, n);
    k_final<<<1, 1>>>(log_lambda, log_alpha, out, n);
}

// round 5
// speedup vs baseline: 1.0920x; 1.0920x over previous
#include <cuda_runtime.h>
#include <math.h>

#define HID 64
#define BD  128

__device__ double g_sums[2];   // [0] = sum (pred-y)^2, [1] = sum residual^2

__global__ void k_zero() { g_sums[0] = 0.0; g_sums[1] = 0.0; }

// Fast, branch-free tanh (abs err ~1e-6), matches R3 accuracy (rel_err 9e-8 overall).
__device__ __forceinline__ float my_tanhf(float z) {
    float zc = fminf(fmaxf(z, -15.f), 15.f);
    float e  = __expf(2.f * zc);
    return 1.f - __fdividef(2.f, e + 1.f);
}

// ---- packed f32x2 helpers (FFMA2 path, sm_100+) ----------------------------
__device__ __forceinline__ unsigned long long dup2(float v) {
    unsigned long long r;
    asm("mov.b64 %0, {%1, %1};" : "=l"(r) : "f"(v));
    return r;
}
__device__ __forceinline__ unsigned long long pack2(float lo, float hi) {
    unsigned long long r;
    asm("mov.b64 %0, {%1, %2};" : "=l"(r) : "f"(lo), "f"(hi));
    return r;
}
__device__ __forceinline__ void ffma2(unsigned long long& a,
                                      unsigned long long x, unsigned long long y) {
    asm("fma.rn.f32x2 %0, %1, %2, %0;" : "+l"(a) : "l"(x), "l"(y));
}
__device__ __forceinline__ float2 unpk(unsigned long long a) {
    float2 f;
    asm("mov.b64 {%0, %1}, %2;" : "=f"(f.x), "=f"(f.y) : "l"(a));
    return f;
}

// z_j += sum_i st[i] * W[i][j], j = 0..63, as 32 f32x2 pairs.
// st: per-thread state column in SMEM; wsh: 64x64 weight tile in SMEM.
__device__ __forceinline__ void matvec(const float* st, const float* wsh,
                                       unsigned long long* zp, int tid) {
    #pragma unroll 4
    for (int i = 0; i < HID; i++) {
        unsigned long long vp = dup2(st[i * BD + tid]);
        const ulonglong2* wr = (const ulonglong2*)(wsh + (i << 6));
        #pragma unroll
        for (int c = 0; c < 16; c++) {
            ulonglong2 w = wr[c];           // LDS.128 broadcast: pairs (4c,4c+1),(4c+2,4c+3)
            ffma2(zp[2 * c],     vp, w.x);
            ffma2(zp[2 * c + 1], vp, w.y);
        }
    }
}

// Cooperatively stage a 64x64 weight matrix into SMEM.
__device__ __forceinline__ void stage_w(float* wsh, const float* __restrict__ W, int tid) {
    __syncthreads();                        // prior readers of wsh are done
    const float4* src = (const float4*)W;
    float4*       dst = (float4*)wsh;
    #pragma unroll
    for (int k = 0; k < (HID * HID / 4) / BD; k++)   // 8 float4 per thread
        dst[k * BD + tid] = src[k * BD + tid];
    __syncthreads();
}

__device__ __forceinline__ void block_reduce_atomic(double v, double* slot, float* shbase) {
    #pragma unroll
    for (int off = 16; off; off >>= 1)
        v += __shfl_down_sync(0xffffffffu, v, off);
    __syncthreads();                        // state reads done before scratch reuse
    double* red = (double*)shbase;
    int lane = threadIdx.x & 31, wid = threadIdx.x >> 5;
    if (lane == 0) red[wid] = v;
    __syncthreads();
    if (threadIdx.x == 0) {
        double s = 0.0;
        #pragma unroll
        for (int w = 0; w < BD / 32; w++) s += red[w];
        atomicAdd(slot, s);
    }
}

// ============================================================================
// Fused physics kernel: one pass propagating 6 channels
//   ch0 = h (value), ch1 = ut, ch2 = ux, ch3 = uy, ch4 = wxx, ch5 = wyy
// Channels are serialized per layer (z fits in 32 f32x2 pairs = 64 regs);
// activation coupling handled in epilogues. ux/uy slots hold RAW z between
// their matvec and the corresponding w-channel epilogue, which finalizes both.
// ============================================================================
__global__ __launch_bounds__(BD) void k_phys(
    const float* __restrict__ xin,
    const float* __restrict__ W0, const float* __restrict__ b0,
    const float* __restrict__ W1, const float* __restrict__ b1,
    const float* __restrict__ W2, const float* __restrict__ b2,
    const float* __restrict__ W3, const float* __restrict__ b3,
    const float* __restrict__ W4, const float* __restrict__ b4,
    const float* __restrict__ log_alpha,
    int n)
{
    extern __shared__ float sh[];
    float* st  = sh;                        // 6 channels x [HID][BD]
    float* wsh = sh + 6 * HID * BD;         // 64x64 staged weights
    const int tid = threadIdx.x;
    const int p   = blockIdx.x * BD + tid;
    const bool active = p < n;

    float x0 = 0.f, x1 = 0.f, x2 = 0.f;
    if (active) { x0 = xin[3 * p]; x1 = xin[3 * p + 1]; x2 = xin[3 * p + 2]; }

    // ---- layer 0: 3 -> 64. Tangents: ux<-e_x, uy<-e_y, ut<-e_t; zw = 0 ----
    #pragma unroll 8
    for (int j = 0; j < HID; j++) {
        float wx = __ldg(W0 + j);
        float wy = __ldg(W0 + HID + j);
        float wt = __ldg(W0 + 2 * HID + j);
        float zh = __ldg(b0 + j) + x0 * wx + x1 * wy + x2 * wt;
        float t = my_tanhf(zh);
        float s = 1.f - t * t;
        st[(0 * HID + j) * BD + tid] = t;
        st[(1 * HID + j) * BD + tid] = s * wt;                 // ut
        st[(2 * HID + j) * BD + tid] = s * wx;                 // ux
        st[(3 * HID + j) * BD + tid] = s * wy;                 // uy
        st[(4 * HID + j) * BD + tid] = -2.f * t * s * wx * wx; // wxx
        st[(5 * HID + j) * BD + tid] = -2.f * t * s * wy * wy; // wyy
    }

    // ---- hidden layers 1..3 ----
    #pragma unroll 1
    for (int l = 0; l < 3; l++) {
        const float* W  = (l == 0) ? W1 : (l == 1) ? W2 : W3;
        const float* bb = (l == 0) ? b1 : (l == 1) ? b2 : b3;
        stage_w(wsh, W, tid);

        unsigned long long zp[32];

        // --- H: z = b + h_old @ W; h_new = tanh(z) ---
        #pragma unroll
        for (int c = 0; c < 32; c++) {
            float2 bv = __ldg((const float2*)bb + c);
            zp[c] = pack2(bv.x, bv.y);
        }
        matvec(st + 0 * HID * BD, wsh, zp, tid);
        #pragma unroll
        for (int c = 0; c < 32; c++) {
            float2 z = unpk(zp[c]);
            st[(0 * HID + 2 * c)     * BD + tid] = my_tanhf(z.x);
            st[(0 * HID + 2 * c + 1) * BD + tid] = my_tanhf(z.y);
        }

        // --- UT: ut_new = s * z ---
        #pragma unroll
        for (int c = 0; c < 32; c++) zp[c] = 0ull;
        matvec(st + 1 * HID * BD, wsh, zp, tid);
        #pragma unroll
        for (int c = 0; c < 32; c++) {
            float2 z = unpk(zp[c]);
            float h0 = st[(0 * HID + 2 * c)     * BD + tid];
            float h1 = st[(0 * HID + 2 * c + 1) * BD + tid];
            st[(1 * HID + 2 * c)     * BD + tid] = (1.f - h0 * h0) * z.x;
            st[(1 * HID + 2 * c + 1) * BD + tid] = (1.f - h1 * h1) * z.y;
        }

        // --- UX: store RAW z (needed by WXX epilogue) ---
        #pragma unroll
        for (int c = 0; c < 32; c++) zp[c] = 0ull;
        matvec(st + 2 * HID * BD, wsh, zp, tid);
        #pragma unroll
        for (int c = 0; c < 32; c++) {
            float2 z = unpk(zp[c]);
            st[(2 * HID + 2 * c)     * BD + tid] = z.x;
            st[(2 * HID + 2 * c + 1) * BD + tid] = z.y;
        }

        // --- WXX: wxx_new = s*z - 2*t*s*zx^2 ; also finalize ux = s*zx ---
        #pragma unroll
        for (int c = 0; c < 32; c++) zp[c] = 0ull;
        matvec(st + 4 * HID * BD, wsh, zp, tid);
        #pragma unroll
        for (int c = 0; c < 32; c++) {
            float2 z = unpk(zp[c]);
            #pragma unroll
            for (int hh = 0; hh < 2; hh++) {
                int j = 2 * c + hh;
                float zw = hh ? z.y : z.x;
                float t  = st[(0 * HID + j) * BD + tid];
                float zx = st[(2 * HID + j) * BD + tid];
                float s  = 1.f - t * t;
                float sz = s * zx;
                st[(4 * HID + j) * BD + tid] = s * zw - 2.f * t * zx * sz;
                st[(2 * HID + j) * BD + tid] = sz;
            }
        }

        // --- UY: store RAW z ---
        #pragma unroll
        for (int c = 0; c < 32; c++) zp[c] = 0ull;
        matvec(st + 3 * HID * BD, wsh, zp, tid);
        #pragma unroll
        for (int c = 0; c < 32; c++) {
            float2 z = unpk(zp[c]);
            st[(3 * HID + 2 * c)     * BD + tid] = z.x;
            st[(3 * HID + 2 * c + 1) * BD + tid] = z.y;
        }

        // --- WYY: wyy_new = s*z - 2*t*s*zy^2 ; finalize uy = s*zy ---
        #pragma unroll
        for (int c = 0; c < 32; c++) zp[c] = 0ull;
        matvec(st + 5 * HID * BD, wsh, zp, tid);
        #pragma unroll
        for (int c = 0; c < 32; c++) {
            float2 z = unpk(zp[c]);
            #pragma unroll
            for (int hh = 0; hh < 2; hh++) {
                int j = 2 * c + hh;
                float zw = hh ? z.y : z.x;
                float t  = st[(0 * HID + j) * BD + tid];
                float zy = st[(3 * HID + j) * BD + tid];
                float s  = 1.f - t * t;
                float sz = s * zy;
                st[(5 * HID + j) * BD + tid] = s * zw - 2.f * t * zy * sz;
                st[(3 * HID + j) * BD + tid] = sz;
            }
        }
    }

    // ---- output layer (linear): only ut, wxx, wyy matter for the residual ----
    float at = 0.f, axx = 0.f, ayy = 0.f;
    #pragma unroll 8
    for (int i = 0; i < HID; i++) {
        float w = __ldg(W4 + i);
        at  += st[(1 * HID + i) * BD + tid] * w;
        axx += st[(4 * HID + i) * BD + tid] * w;
        ayy += st[(5 * HID + i) * BD + tid] * w;
    }

    double local = 0.0;
    if (active) {
        float alpha = expf(__ldg(log_alpha));
        float r = at - alpha * (axx + ayy);
        local = (double)r * (double)r;
    }
    block_reduce_atomic(local, &g_sums[1], sh);
}

// ============================================================================
// Data-loss kernel: value channel only
// ============================================================================
__global__ __launch_bounds__(BD) void k_data(
    const float* __restrict__ xin,
    const float* __restrict__ ydata,
    const float* __restrict__ W0, const float* __restrict__ b0,
    const float* __restrict__ W1, const float* __restrict__ b1,
    const float* __restrict__ W2, const float* __restrict__ b2,
    const float* __restrict__ W3, const float* __restrict__ b3,
    const float* __restrict__ W4, const float* __restrict__ b4,
    int n)
{
    extern __shared__ float sh[];
    float* st  = sh;                  // [HID][BD]
    float* wsh = sh + HID * BD;
    const int tid = threadIdx.x;
    const int p   = blockIdx.x * BD + tid;
    const bool active = p < n;

    float x0 = 0.f, x1 = 0.f, x2 = 0.f;
    if (active) { x0 = xin[3 * p]; x1 = xin[3 * p + 1]; x2 = xin[3 * p + 2]; }

    #pragma unroll 8
    for (int j = 0; j < HID; j++) {
        float zh = __ldg(b0 + j) + x0 * __ldg(W0 + j)
                                 + x1 * __ldg(W0 + HID + j)
                                 + x2 * __ldg(W0 + 2 * HID + j);
        st[j * BD + tid] = my_tanhf(zh);
    }

    #pragma unroll 1
    for (int l = 0; l < 3; l++) {
        const float* W  = (l == 0) ? W1 : (l == 1) ? W2 : W3;
        const float* bb = (l == 0) ? b1 : (l == 1) ? b2 : b3;
        stage_w(wsh, W, tid);

        unsigned long long zp[32];
        #pragma unroll
        for (int c = 0; c < 32; c++) {
            float2 bv = __ldg((const float2*)bb + c);
            zp[c] = pack2(bv.x, bv.y);
        }
        matvec(st, wsh, zp, tid);
        #pragma unroll
        for (int c = 0; c < 32; c++) {
            float2 z = unpk(zp[c]);
            st[(2 * c)     * BD + tid] = my_tanhf(z.x);
            st[(2 * c + 1) * BD + tid] = my_tanhf(z.y);
        }
    }

    float ah = __ldg(b4);
    #pragma unroll 8
    for (int i = 0; i < HID; i++)
        ah += st[i * BD + tid] * __ldg(W4 + i);

    double local = 0.0;
    if (active) {
        float d = ah - ydata[p];
        local = (double)d * (double)d;
    }
    block_reduce_atomic(local, &g_sums[0], sh);
}

__global__ void k_final(const float* __restrict__ log_lambda,
                        const float* __restrict__ log_alpha,
                        float* __restrict__ out, int n)
{
    float data_loss = (float)(g_sums[0] / (double)n);
    float pde_loss  = (float)(g_sums[1] / (double)n);
    float alpha = expf(log_alpha[0]);
    float lam   = expf(log_lambda[0]);
    out[0] = data_loss + lam * pde_loss;
    out[1] = data_loss;
    out[2] = pde_loss;
    out[3] = alpha;
    out[4] = lam;
}

extern "C" void kernel_launch(void* const* d_in, const int* in_sizes, int n_in,
                              void* d_out, int out_size)
{
    const float* x_data     = (const float*)d_in[0];
    const float* y_data     = (const float*)d_in[1];
    const float* x_phys     = (const float*)d_in[2];
    const float* W0 = (const float*)d_in[3];  const float* b0 = (const float*)d_in[4];
    const float* W1 = (const float*)d_in[5];  const float* b1 = (const float*)d_in[6];
    const float* W2 = (const float*)d_in[7];  const float* b2 = (const float*)d_in[8];
    const float* W3 = (const float*)d_in[9];  const float* b3 = (const float*)d_in[10];
    const float* W4 = (const float*)d_in[11]; const float* b4 = (const float*)d_in[12];
    const float* log_lambda = (const float*)d_in[13];
    const float* log_alpha  = (const float*)d_in[14];
    float* out = (float*)d_out;

    int n = in_sizes[0] / 3;
    int grid = (n + BD - 1) / BD;

    const int SH_DATA = (HID * BD + HID * HID) * (int)sizeof(float);      // 48 KB
    const int SH_PHYS = (6 * HID * BD + HID * HID) * (int)sizeof(float);  // 208 KB

    cudaFuncSetAttribute(k_data, cudaFuncAttributeMaxDynamicSharedMemorySize, SH_DATA);
    cudaFuncSetAttribute(k_phys, cudaFuncAttributeMaxDynamicSharedMemorySize, SH_PHYS);

    k_zero<<<1, 1>>>();
    k_data<<<grid, BD, SH_DATA>>>(x_data, y_data, W0, b0, W1, b1, W2, b2,
                                  W3, b3, W4, b4, n);
    k_phys<<<grid, BD, SH_PHYS>>>(x_phys, W0, b0, W1, b1, W2, b2,
                                  W3, b3, W4, b4, log_alpha, n);
    k_final<<<1, 1>>>(log_lambda, log_alpha, out, n);
}

// round 8
// speedup vs baseline: 1.6867x; 1.5446x over previous
#include <cuda_runtime.h>
#include <math.h>

#define HID 64
#define PTS 128      // points per phys CTA
#define BDP 256      // phys block: 2 threads per point (j split in halves of 32)
#define BD  128      // data block

__device__ double g_sums[2];   // [0] = sum (pred-y)^2, [1] = sum residual^2

__global__ void k_zero() { g_sums[0] = 0.0; g_sums[1] = 0.0; }

// Fast, branch-free tanh (abs err ~1e-6).
__device__ __forceinline__ float my_tanhf(float z) {
    float zc = fminf(fmaxf(z, -15.f), 15.f);
    float e  = __expf(2.f * zc);
    return 1.f - __fdividef(2.f, e + 1.f);
}

// ---- packed f32x2 helpers (FFMA2 path, sm_100+) ----------------------------
__device__ __forceinline__ unsigned long long dup2(float v) {
    unsigned long long r;
    asm("mov.b64 %0, {%1, %1};" : "=l"(r) : "f"(v));
    return r;
}
__device__ __forceinline__ unsigned long long pack2(float lo, float hi) {
    unsigned long long r;
    asm("mov.b64 %0, {%1, %2};" : "=l"(r) : "f"(lo), "f"(hi));
    return r;
}
__device__ __forceinline__ void ffma2(unsigned long long& a,
                                      unsigned long long x, unsigned long long y) {
    asm("fma.rn.f32x2 %0, %1, %2, %0;" : "+l"(a) : "l"(x), "l"(y));
}
__device__ __forceinline__ float2 unpk(unsigned long long a) {
    float2 f;
    asm("mov.b64 {%0, %1}, %2;" : "=f"(f.x), "=f"(f.y) : "l"(a));
    return f;
}

// z_j += sum_{i=0..63} stc[i][pt] * W[i][jbase+jj], jj=0..31, as 16 f32x2 pairs.
__device__ __forceinline__ void matvec_half(const float* __restrict__ stc,
                                            const float* __restrict__ wsh,
                                            unsigned long long* zp,
                                            int pt, int jbase) {
    #pragma unroll 4
    for (int i = 0; i < HID; i++) {
        unsigned long long vp = dup2(stc[i * PTS + pt]);
        const ulonglong2* wr = (const ulonglong2*)(wsh + i * HID + jbase);
        #pragma unroll
        for (int k = 0; k < 8; k++) {
            ulonglong2 w = wr[k];        // LDS.128 broadcast
            ffma2(zp[2 * k],     vp, w.x);
            ffma2(zp[2 * k + 1], vp, w.y);
        }
    }
}

// ============================================================================
// Fused physics kernel. 6 channels: 0=h 1=ut 2=ux 3=uy 4=wxx 5=wyy.
// 2 threads per point; thread owns 32 output neurons per layer.
// ============================================================================
__global__ __launch_bounds__(BDP, 1) void k_phys(
    const float* __restrict__ xin,
    const float* __restrict__ W0, const float* __restrict__ b0,
    const float* __restrict__ W1, const float* __restrict__ b1,
    const float* __restrict__ W2, const float* __restrict__ b2,
    const float* __restrict__ W3, const float* __restrict__ b3,
    const float* __restrict__ W4, const float* __restrict__ b4,
    const float* __restrict__ log_alpha,
    int n)
{
    extern __shared__ float sh[];
    float* st  = sh;                        // [6][HID][PTS]
    float* wsh = sh + 6 * HID * PTS;        // 64x64 staged weights (also rp buffer)
    const int tid   = threadIdx.x;
    const int pt    = tid & (PTS - 1);
    const int half  = tid >> 7;             // 0 or 1
    const int jbase = half << 5;            // 0 or 32
    const int p     = blockIdx.x * PTS + pt;
    const bool active = p < n;

    float x0 = 0.f, x1 = 0.f, x2 = 0.f;
    if (active) { x0 = xin[3 * p]; x1 = xin[3 * p + 1]; x2 = xin[3 * p + 2]; }

    // ---- layer 0: 3 -> 64, own 32 neurons ----
    #pragma unroll 8
    for (int jj = 0; jj < 32; jj++) {
        int j = jbase + jj;
        float wx = __ldg(W0 + j);
        float wy = __ldg(W0 + HID + j);
        float wt = __ldg(W0 + 2 * HID + j);
        float zh = __ldg(b0 + j) + x0 * wx + x1 * wy + x2 * wt;
        float t = my_tanhf(zh);
        float s = 1.f - t * t;
        st[(0 * HID + j) * PTS + pt] = t;
        st[(1 * HID + j) * PTS + pt] = s * wt;                 // ut
        st[(2 * HID + j) * PTS + pt] = s * wx;                 // ux
        st[(3 * HID + j) * PTS + pt] = s * wy;                 // uy
        st[(4 * HID + j) * PTS + pt] = -2.f * t * s * wx * wx; // wxx
        st[(5 * HID + j) * PTS + pt] = -2.f * t * s * wy * wy; // wyy
    }

    // ---- hidden layers 1..3 ----
    #pragma unroll 1
    for (int l = 0; l < 3; l++) {
        const float* W  = (l == 0) ? W1 : (l == 1) ? W2 : W3;
        const float* bb = (l == 0) ? b1 : (l == 1) ? b2 : b3;

        // stage weights (sync orders previous epilogue writes too)
        __syncthreads();
        {
            const float4* src = (const float4*)W;
            float4*       dst = (float4*)wsh;
            #pragma unroll
            for (int k = 0; k < (HID * HID / 4) / BDP; k++)   // 4 float4/thread
                dst[k * BDP + tid] = src[k * BDP + tid];
        }
        __syncthreads();

        unsigned long long zp[16];

        // --- H ---
        #pragma unroll
        for (int m = 0; m < 16; m++) {
            float2 bv = __ldg((const float2*)bb + (jbase >> 1) + m);
            zp[m] = pack2(bv.x, bv.y);
        }
        matvec_half(st + 0 * HID * PTS, wsh, zp, pt, jbase);
        __syncthreads();
        #pragma unroll
        for (int m = 0; m < 16; m++) {
            float2 z = unpk(zp[m]);
            int j0 = jbase + 2 * m;
            st[(0 * HID + j0)     * PTS + pt] = my_tanhf(z.x);
            st[(0 * HID + j0 + 1) * PTS + pt] = my_tanhf(z.y);
        }

        // --- UT: ut_new = s * z ---
        #pragma unroll
        for (int m = 0; m < 16; m++) zp[m] = 0ull;
        matvec_half(st + 1 * HID * PTS, wsh, zp, pt, jbase);
        __syncthreads();
        #pragma unroll
        for (int m = 0; m < 16; m++) {
            float2 z = unpk(zp[m]);
            int j0 = jbase + 2 * m;
            float h0 = st[(0 * HID + j0)     * PTS + pt];
            float h1 = st[(0 * HID + j0 + 1) * PTS + pt];
            st[(1 * HID + j0)     * PTS + pt] = (1.f - h0 * h0) * z.x;
            st[(1 * HID + j0 + 1) * PTS + pt] = (1.f - h1 * h1) * z.y;
        }

        // --- UX: store RAW z (WXX epilogue finalizes) ---
        #pragma unroll
        for (int m = 0; m < 16; m++) zp[m] = 0ull;
        matvec_half(st + 2 * HID * PTS, wsh, zp, pt, jbase);
        __syncthreads();
        #pragma unroll
        for (int m = 0; m < 16; m++) {
            float2 z = unpk(zp[m]);
            int j0 = jbase + 2 * m;
            st[(2 * HID + j0)     * PTS + pt] = z.x;
            st[(2 * HID + j0 + 1) * PTS + pt] = z.y;
        }

        // --- WXX: wxx_new = s*zw - 2*t*zx*(s*zx); finalize ux = s*zx ---
        #pragma unroll
        for (int m = 0; m < 16; m++) zp[m] = 0ull;
        matvec_half(st + 4 * HID * PTS, wsh, zp, pt, jbase);
        __syncthreads();
        #pragma unroll
        for (int m = 0; m < 16; m++) {
            float2 z = unpk(zp[m]);
            #pragma unroll
            for (int hh = 0; hh < 2; hh++) {
                int j = jbase + 2 * m + hh;
                float zw = hh ? z.y : z.x;
                float t  = st[(0 * HID + j) * PTS + pt];
                float zx = st[(2 * HID + j) * PTS + pt];
                float s  = 1.f - t * t;
                float sz = s * zx;
                st[(4 * HID + j) * PTS + pt] = s * zw - 2.f * t * zx * sz;
                st[(2 * HID + j) * PTS + pt] = sz;
            }
        }

        // --- UY: store RAW z ---
        #pragma unroll
        for (int m = 0; m < 16; m++) zp[m] = 0ull;
        matvec_half(st + 3 * HID * PTS, wsh, zp, pt, jbase);
        __syncthreads();
        #pragma unroll
        for (int m = 0; m < 16; m++) {
            float2 z = unpk(zp[m]);
            int j0 = jbase + 2 * m;
            st[(3 * HID + j0)     * PTS + pt] = z.x;
            st[(3 * HID + j0 + 1) * PTS + pt] = z.y;
        }

        // --- WYY: wyy_new = s*zw - 2*t*zy*(s*zy); finalize uy = s*zy ---
        #pragma unroll
        for (int m = 0; m < 16; m++) zp[m] = 0ull;
        matvec_half(st + 5 * HID * PTS, wsh, zp, pt, jbase);
        __syncthreads();
        #pragma unroll
        for (int m = 0; m < 16; m++) {
            float2 z = unpk(zp[m]);
            #pragma unroll
            for (int hh = 0; hh < 2; hh++) {
                int j = jbase + 2 * m + hh;
                float zw = hh ? z.y : z.x;
                float t  = st[(0 * HID + j) * PTS + pt];
                float zy = st[(3 * HID + j) * PTS + pt];
                float s  = 1.f - t * t;
                float sz = s * zy;
                st[(5 * HID + j) * PTS + pt] = s * zw - 2.f * t * zy * sz;
                st[(3 * HID + j) * PTS + pt] = sz;
            }
        }
    }

    // ---- output layer: partial over own 32 neurons (all self-written) ----
    float at = 0.f, axx = 0.f, ayy = 0.f;
    #pragma unroll 8
    for (int jj = 0; jj < 32; jj++) {
        int j = jbase + jj;
        float w = __ldg(W4 + j);
        at  += st[(1 * HID + j) * PTS + pt] * w;
        axx += st[(4 * HID + j) * PTS + pt] * w;
        ayy += st[(5 * HID + j) * PTS + pt] * w;
    }
    float alpha = expf(__ldg(log_alpha));
    float rp = at - alpha * (axx + ayy);      // partial residual (alpha is linear)

    __syncthreads();                          // wsh reads all retired (last bar passed)
    wsh[half * PTS + pt] = rp;
    __syncthreads();

    double local = 0.0;
    if (half == 0 && active) {
        float r = rp + wsh[PTS + pt];
        local = (double)r * (double)r;
    }

    // block reduction -> atomic
    #pragma unroll
    for (int off = 16; off; off >>= 1)
        local += __shfl_down_sync(0xffffffffu, local, off);
    __syncthreads();
    double* red = (double*)sh;
    int lane = tid & 31, wid = tid >> 5;
    if (lane == 0) red[wid] = local;
    __syncthreads();
    if (tid == 0) {
        double s = 0.0;
        #pragma unroll
        for (int w = 0; w < BDP / 32; w++) s += red[w];
        atomicAdd(&g_sums[1], s);
    }
}

// ============================================================================
// Data-loss kernel (value only): 48 KB smem -> 4 CTAs/SM, latency well hidden.
// ============================================================================
__global__ __launch_bounds__(BD) void k_data(
    const float* __restrict__ xin,
    const float* __restrict__ ydata,
    const float* __restrict__ W0, const float* __restrict__ b0,
    const float* __restrict__ W1, const float* __restrict__ b1,
    const float* __restrict__ W2, const float* __restrict__ b2,
    const float* __restrict__ W3, const float* __restrict__ b3,
    const float* __restrict__ W4, const float* __restrict__ b4,
    int n)
{
    extern __shared__ float sh[];
    float* st  = sh;                  // [HID][BD]
    float* wsh = sh + HID * BD;
    const int tid = threadIdx.x;
    const int p   = blockIdx.x * BD + tid;
    const bool active = p < n;

    float x0 = 0.f, x1 = 0.f, x2 = 0.f;
    if (active) { x0 = xin[3 * p]; x1 = xin[3 * p + 1]; x2 = xin[3 * p + 2]; }

    #pragma unroll 8
    for (int j = 0; j < HID; j++) {
        float zh = __ldg(b0 + j) + x0 * __ldg(W0 + j)
                                 + x1 * __ldg(W0 + HID + j)
                                 + x2 * __ldg(W0 + 2 * HID + j);
        st[j * BD + tid] = my_tanhf(zh);
    }

    #pragma unroll 1
    for (int l = 0; l < 3; l++) {
        const float* W  = (l == 0) ? W1 : (l == 1) ? W2 : W3;
        const float* bb = (l == 0) ? b1 : (l == 1) ? b2 : b3;
        __syncthreads();
        {
            const float4* src = (const float4*)W;
            float4*       dst = (float4*)wsh;
            #pragma unroll
            for (int k = 0; k < (HID * HID / 4) / BD; k++)
                dst[k * BD + tid] = src[k * BD + tid];
        }
        __syncthreads();

        unsigned long long zp[32];
        #pragma unroll
        for (int c = 0; c < 32; c++) {
            float2 bv = __ldg((const float2*)bb + c);
            zp[c] = pack2(bv.x, bv.y);
        }
        #pragma unroll 4
        for (int i = 0; i < HID; i++) {
            unsigned long long vp = dup2(st[i * BD + tid]);
            const ulonglong2* wr = (const ulonglong2*)(wsh + (i << 6));
            #pragma unroll
            for (int c = 0; c < 16; c++) {
                ulonglong2 w = wr[c];
                ffma2(zp[2 * c],     vp, w.x);
                ffma2(zp[2 * c + 1], vp, w.y);
            }
        }
        __syncthreads();
        #pragma unroll
        for (int c = 0; c < 32; c++) {
            float2 z = unpk(zp[c]);
            st[(2 * c)     * BD + tid] = my_tanhf(z.x);
            st[(2 * c + 1) * BD + tid] = my_tanhf(z.y);
        }
    }

    float ah = __ldg(b4);
    #pragma unroll 8
    for (int i = 0; i < HID; i++)
        ah += st[i * BD + tid] * __ldg(W4 + i);

    double local = 0.0;
    if (active) {
        float d = ah - ydata[p];
        local = (double)d * (double)d;
    }
    #pragma unroll
    for (int off = 16; off; off >>= 1)
        local += __shfl_down_sync(0xffffffffu, local, off);
    __syncthreads();
    double* red = (double*)sh;
    int lane = tid & 31, wid = tid >> 5;
    if (lane == 0) red[wid] = local;
    __syncthreads();
    if (tid == 0) {
        double s = 0.0;
        #pragma unroll
        for (int w = 0; w < BD / 32; w++) s += red[w];
        atomicAdd(&g_sums[0], s);
    }
}

__global__ void k_final(const float* __restrict__ log_lambda,
                        const float* __restrict__ log_alpha,
                        float* __restrict__ out, int n)
{
    float data_loss = (float)(g_sums[0] / (double)n);
    float pde_loss  = (float)(g_sums[1] / (double)n);
    float alpha = expf(log_alpha[0]);
    float lam   = expf(log_lambda[0]);
    out[0] = data_loss + lam * pde_loss;
    out[1] = data_loss;
    out[2] = pde_loss;
    out[3] = alpha;
    out[4] = lam;
}

extern "C" void kernel_launch(void* const* d_in, const int* in_sizes, int n_in,
                              void* d_out, int out_size)
{
    const float* x_data     = (const float*)d_in[0];
    const float* y_data     = (const float*)d_in[1];
    const float* x_phys     = (const float*)d_in[2];
    const float* W0 = (const float*)d_in[3];  const float* b0 = (const float*)d_in[4];
    const float* W1 = (const float*)d_in[5];  const float* b1 = (const float*)d_in[6];
    const float* W2 = (const float*)d_in[7];  const float* b2 = (const float*)d_in[8];
    const float* W3 = (const float*)d_in[9];  const float* b3 = (const float*)d_in[10];
    const float* W4 = (const float*)d_in[11]; const float* b4 = (const float*)d_in[12];
    const float* log_lambda = (const float*)d_in[13];
    const float* log_alpha  = (const float*)d_in[14];
    float* out = (float*)d_out;

    int n = in_sizes[0] / 3;

    const int SH_DATA = (HID * BD + HID * HID) * (int)sizeof(float);      // 48 KB
    const int SH_PHYS = (6 * HID * PTS + HID * HID) * (int)sizeof(float); // 208 KB

    cudaFuncSetAttribute(k_data, cudaFuncAttributeMaxDynamicSharedMemorySize, SH_DATA);
    cudaFuncSetAttribute(k_phys, cudaFuncAttributeMaxDynamicSharedMemorySize, SH_PHYS);

    int grid_d = (n + BD - 1) / BD;
    int grid_p = (n + PTS - 1) / PTS;

    k_zero<<<1, 1>>>();
    k_data<<<grid_d, BD, SH_DATA>>>(x_data, y_data, W0, b0, W1, b1, W2, b2,
                                    W3, b3, W4, b4, n);
    k_phys<<<grid_p, BDP, SH_PHYS>>>(x_phys, W0, b0, W1, b1, W2, b2,
                                     W3, b3, W4, b4, log_alpha, n);
    k_final<<<1, 1>>>(log_lambda, log_alpha, out, n);
}

// round 9
// speedup vs baseline: 2.3637x; 1.4013x over previous
#include <cuda_runtime.h>
#include <math.h>

#define HID 64
#define PTS 128      // points per phys CTA
#define BDP 512      // phys block: 4 threads per point (j split in quarters of 16)
#define BD  128      // data block

__device__ double g_sums[2];   // [0] = sum (pred-y)^2, [1] = sum residual^2

__global__ void k_zero() { g_sums[0] = 0.0; g_sums[1] = 0.0; }

// Fast, branch-free tanh (abs err ~1e-6).
__device__ __forceinline__ float my_tanhf(float z) {
    float zc = fminf(fmaxf(z, -15.f), 15.f);
    float e  = __expf(2.f * zc);
    return 1.f - __fdividef(2.f, e + 1.f);
}

// ---- packed f32x2 helpers (FFMA2 path, sm_100+) ----------------------------
__device__ __forceinline__ unsigned long long dup2(float v) {
    unsigned long long r;
    asm("mov.b64 %0, {%1, %1};" : "=l"(r) : "f"(v));
    return r;
}
__device__ __forceinline__ unsigned long long pack2(float lo, float hi) {
    unsigned long long r;
    asm("mov.b64 %0, {%1, %2};" : "=l"(r) : "f"(lo), "f"(hi));
    return r;
}
__device__ __forceinline__ void ffma2(unsigned long long& a,
                                      unsigned long long x, unsigned long long y) {
    asm("fma.rn.f32x2 %0, %1, %2, %0;" : "+l"(a) : "l"(x), "l"(y));
}
__device__ __forceinline__ float2 unpk(unsigned long long a) {
    float2 f;
    asm("mov.b64 {%0, %1}, %2;" : "=f"(f.x), "=f"(f.y) : "l"(a));
    return f;
}

// Paired matvec: zA_j += sum_i stA[i]*W[i][j], zB_j += sum_i stB[i]*W[i][j],
// for the 16 owned j (8 f32x2 pairs each). One weight load serves both channels.
__device__ __forceinline__ void matvec2(const float* __restrict__ stA,
                                        const float* __restrict__ stB,
                                        const float* __restrict__ wsh,
                                        unsigned long long* zA,
                                        unsigned long long* zB,
                                        int pt, int jbase) {
    #pragma unroll 4
    for (int i = 0; i < HID; i++) {
        unsigned long long vA = dup2(stA[i * PTS + pt]);
        unsigned long long vB = dup2(stB[i * PTS + pt]);
        const ulonglong2* wr = (const ulonglong2*)(wsh + i * HID + jbase);
        #pragma unroll
        for (int k = 0; k < 4; k++) {
            ulonglong2 w = wr[k];            // LDS.128 broadcast
            ffma2(zA[2 * k],     vA, w.x);
            ffma2(zA[2 * k + 1], vA, w.y);
            ffma2(zB[2 * k],     vB, w.x);
            ffma2(zB[2 * k + 1], vB, w.y);
        }
    }
}

// Single-channel matvec for the Laplacian pass.
__device__ __forceinline__ void matvec1(const float* __restrict__ stA,
                                        const float* __restrict__ wsh,
                                        unsigned long long* zA,
                                        int pt, int jbase) {
    #pragma unroll 4
    for (int i = 0; i < HID; i++) {
        unsigned long long vA = dup2(stA[i * PTS + pt]);
        const ulonglong2* wr = (const ulonglong2*)(wsh + i * HID + jbase);
        #pragma unroll
        for (int k = 0; k < 4; k++) {
            ulonglong2 w = wr[k];
            ffma2(zA[2 * k],     vA, w.x);
            ffma2(zA[2 * k + 1], vA, w.y);
        }
    }
}

// ============================================================================
// Fused physics kernel, Laplacian formulation. Channels:
//   0=h  1=ut  2=ux  3=uy  4=L (Laplacian)  5=q scratch (zx^2+zy^2)
// 4 threads per point; each owns 16 output neurons per layer.
// Per layer: pass1=(h,ut) paired, pass2=(ux,uy) paired, pass3=L.
// ============================================================================
__global__ __launch_bounds__(BDP, 1) void k_phys(
    const float* __restrict__ xin,
    const float* __restrict__ W0, const float* __restrict__ b0,
    const float* __restrict__ W1, const float* __restrict__ b1,
    const float* __restrict__ W2, const float* __restrict__ b2,
    const float* __restrict__ W3, const float* __restrict__ b3,
    const float* __restrict__ W4, const float* __restrict__ b4,
    const float* __restrict__ log_alpha,
    int n)
{
    extern __shared__ float sh[];
    float* st  = sh;                        // [6][HID][PTS]
    float* wsh = sh + 6 * HID * PTS;        // 64x64 staged weights (also rp buffer)
    const int tid   = threadIdx.x;
    const int pt    = tid & (PTS - 1);
    const int quar  = tid >> 7;             // 0..3
    const int jbase = quar << 4;            // 0,16,32,48
    const int p     = blockIdx.x * PTS + pt;
    const bool active = p < n;

    float x0 = 0.f, x1 = 0.f, x2 = 0.f;
    if (active) { x0 = xin[3 * p]; x1 = xin[3 * p + 1]; x2 = xin[3 * p + 2]; }

    // ---- layer 0: 3 -> 64, own 16 neurons. zx=W0x, zy=W0y, zt=W0t; zL=0 ----
    #pragma unroll 4
    for (int jj = 0; jj < 16; jj++) {
        int j = jbase + jj;
        float wx = __ldg(W0 + j);
        float wy = __ldg(W0 + HID + j);
        float wt = __ldg(W0 + 2 * HID + j);
        float zh = __ldg(b0 + j) + x0 * wx + x1 * wy + x2 * wt;
        float t = my_tanhf(zh);
        float s = 1.f - t * t;
        st[(0 * HID + j) * PTS + pt] = t;
        st[(1 * HID + j) * PTS + pt] = s * wt;                         // ut
        st[(2 * HID + j) * PTS + pt] = s * wx;                         // ux
        st[(3 * HID + j) * PTS + pt] = s * wy;                         // uy
        st[(4 * HID + j) * PTS + pt] = -2.f * t * s * (wx*wx + wy*wy); // Laplacian
    }

    // ---- hidden layers 1..3 ----
    #pragma unroll 1
    for (int l = 0; l < 3; l++) {
        const float* W  = (l == 0) ? W1 : (l == 1) ? W2 : W3;
        const float* bb = (l == 0) ? b1 : (l == 1) ? b2 : b3;

        __syncthreads();   // prev-layer epi writes visible; wsh reads retired
        {
            const float4* src = (const float4*)W;
            float4*       dst = (float4*)wsh;
            #pragma unroll
            for (int k = 0; k < (HID * HID / 4) / BDP; k++)   // 2 float4/thread
                dst[k * BDP + tid] = src[k * BDP + tid];
        }
        __syncthreads();

        unsigned long long zA[8], zB[8];

        // --- pass1: (h, ut). zA = b + h@W ; zB = ut@W ---
        #pragma unroll
        for (int m = 0; m < 8; m++) {
            float2 bv = __ldg((const float2*)bb + (jbase >> 1) + m);
            zA[m] = pack2(bv.x, bv.y);
            zB[m] = 0ull;
        }
        matvec2(st + 0 * HID * PTS, st + 1 * HID * PTS, wsh, zA, zB, pt, jbase);
        __syncthreads();                    // all reads of ch0/ch1 done
        #pragma unroll
        for (int m = 0; m < 8; m++) {
            float2 zh = unpk(zA[m]);
            float2 zt = unpk(zB[m]);
            #pragma unroll
            for (int hh = 0; hh < 2; hh++) {
                int j = jbase + 2 * m + hh;
                float t = my_tanhf(hh ? zh.y : zh.x);
                float s = 1.f - t * t;
                st[(0 * HID + j) * PTS + pt] = t;
                st[(1 * HID + j) * PTS + pt] = s * (hh ? zt.y : zt.x);
            }
        }

        // --- pass2: (ux, uy). Epilogue: q = zx^2+zy^2; ux=s*zx; uy=s*zy ---
        // (mv2 reads ch2/ch3 only; epi1 wrote ch0/ch1 — no barrier needed here)
        #pragma unroll
        for (int m = 0; m < 8; m++) { zA[m] = 0ull; zB[m] = 0ull; }
        matvec2(st + 2 * HID * PTS, st + 3 * HID * PTS, wsh, zA, zB, pt, jbase);
        __syncthreads();                    // all reads of ch2/ch3 done
        #pragma unroll
        for (int m = 0; m < 8; m++) {
            float2 zx = unpk(zA[m]);
            float2 zy = unpk(zB[m]);
            #pragma unroll
            for (int hh = 0; hh < 2; hh++) {
                int j = jbase + 2 * m + hh;
                float zxv = hh ? zx.y : zx.x;
                float zyv = hh ? zy.y : zy.x;
                float t = st[(0 * HID + j) * PTS + pt];   // self-written in epi1
                float s = 1.f - t * t;
                st[(2 * HID + j) * PTS + pt] = s * zxv;
                st[(3 * HID + j) * PTS + pt] = s * zyv;
                st[(5 * HID + j) * PTS + pt] = zxv * zxv + zyv * zyv;  // q
            }
        }

        // --- pass3: Laplacian. L_new = s*zL - 2*t*s*q ---
        // (mv3 reads ch4 only; epi2 wrote ch2/3/5 — no barrier needed here)
        #pragma unroll
        for (int m = 0; m < 8; m++) zA[m] = 0ull;
        matvec1(st + 4 * HID * PTS, wsh, zA, pt, jbase);
        __syncthreads();                    // all reads of ch4 done
        #pragma unroll
        for (int m = 0; m < 8; m++) {
            float2 zl = unpk(zA[m]);
            #pragma unroll
            for (int hh = 0; hh < 2; hh++) {
                int j = jbase + 2 * m + hh;
                float zlv = hh ? zl.y : zl.x;
                float t = st[(0 * HID + j) * PTS + pt];
                float q = st[(5 * HID + j) * PTS + pt];   // self-written in epi2
                float s = 1.f - t * t;
                st[(4 * HID + j) * PTS + pt] = s * zlv - 2.f * t * s * q;
            }
        }
    }

    // ---- output layer: partial over own 16 neurons (all self-written) ----
    float at = 0.f, aL = 0.f;
    #pragma unroll 4
    for (int jj = 0; jj < 16; jj++) {
        int j = jbase + jj;
        float w = __ldg(W4 + j);
        at += st[(1 * HID + j) * PTS + pt] * w;
        aL += st[(4 * HID + j) * PTS + pt] * w;
    }
    float alpha = expf(__ldg(log_alpha));
    float rp = at - alpha * aL;             // partial residual (linear in partials)

    wsh[quar * PTS + pt] = rp;              // wsh free (post-mv3 barrier passed)
    __syncthreads();

    double local = 0.0;
    if (quar == 0 && active) {
        float r = rp + wsh[PTS + pt] + wsh[2 * PTS + pt] + wsh[3 * PTS + pt];
        local = (double)r * (double)r;
    }

    // block reduction -> atomic
    #pragma unroll
    for (int off = 16; off; off >>= 1)
        local += __shfl_down_sync(0xffffffffu, local, off);
    __syncthreads();
    double* red = (double*)sh;
    int lane = tid & 31, wid = tid >> 5;
    if (lane == 0) red[wid] = local;
    __syncthreads();
    if (tid == 0) {
        double s = 0.0;
        #pragma unroll
        for (int w = 0; w < BDP / 32; w++) s += red[w];
        atomicAdd(&g_sums[1], s);
    }
}

// ============================================================================
// Data-loss kernel (value only): 48 KB smem -> 4 CTAs/SM.
// ============================================================================
__global__ __launch_bounds__(BD) void k_data(
    const float* __restrict__ xin,
    const float* __restrict__ ydata,
    const float* __restrict__ W0, const float* __restrict__ b0,
    const float* __restrict__ W1, const float* __restrict__ b1,
    const float* __restrict__ W2, const float* __restrict__ b2,
    const float* __restrict__ W3, const float* __restrict__ b3,
    const float* __restrict__ W4, const float* __restrict__ b4,
    int n)
{
    extern __shared__ float sh[];
    float* st  = sh;                  // [HID][BD]
    float* wsh = sh + HID * BD;
    const int tid = threadIdx.x;
    const int p   = blockIdx.x * BD + tid;
    const bool active = p < n;

    float x0 = 0.f, x1 = 0.f, x2 = 0.f;
    if (active) { x0 = xin[3 * p]; x1 = xin[3 * p + 1]; x2 = xin[3 * p + 2]; }

    #pragma unroll 8
    for (int j = 0; j < HID; j++) {
        float zh = __ldg(b0 + j) + x0 * __ldg(W0 + j)
                                 + x1 * __ldg(W0 + HID + j)
                                 + x2 * __ldg(W0 + 2 * HID + j);
        st[j * BD + tid] = my_tanhf(zh);
    }

    #pragma unroll 1
    for (int l = 0; l < 3; l++) {
        const float* W  = (l == 0) ? W1 : (l == 1) ? W2 : W3;
        const float* bb = (l == 0) ? b1 : (l == 1) ? b2 : b3;
        __syncthreads();
        {
            const float4* src = (const float4*)W;
            float4*       dst = (float4*)wsh;
            #pragma unroll
            for (int k = 0; k < (HID * HID / 4) / BD; k++)
                dst[k * BD + tid] = src[k * BD + tid];
        }
        __syncthreads();

        unsigned long long zp[32];
        #pragma unroll
        for (int c = 0; c < 32; c++) {
            float2 bv = __ldg((const float2*)bb + c);
            zp[c] = pack2(bv.x, bv.y);
        }
        #pragma unroll 4
        for (int i = 0; i < HID; i++) {
            unsigned long long vp = dup2(st[i * BD + tid]);
            const ulonglong2* wr = (const ulonglong2*)(wsh + (i << 6));
            #pragma unroll
            for (int c = 0; c < 16; c++) {
                ulonglong2 w = wr[c];
                ffma2(zp[2 * c],     vp, w.x);
                ffma2(zp[2 * c + 1], vp, w.y);
            }
        }
        __syncthreads();
        #pragma unroll
        for (int c = 0; c < 32; c++) {
            float2 z = unpk(zp[c]);
            st[(2 * c)     * BD + tid] = my_tanhf(z.x);
            st[(2 * c + 1) * BD + tid] = my_tanhf(z.y);
        }
    }

    float ah = __ldg(b4);
    #pragma unroll 8
    for (int i = 0; i < HID; i++)
        ah += st[i * BD + tid] * __ldg(W4 + i);

    double local = 0.0;
    if (active) {
        float d = ah - ydata[p];
        local = (double)d * (double)d;
    }
    #pragma unroll
    for (int off = 16; off; off >>= 1)
        local += __shfl_down_sync(0xffffffffu, local, off);
    __syncthreads();
    double* red = (double*)sh;
    int lane = tid & 31, wid = tid >> 5;
    if (lane == 0) red[wid] = local;
    __syncthreads();
    if (tid == 0) {
        double s = 0.0;
        #pragma unroll
        for (int w = 0; w < BD / 32; w++) s += red[w];
        atomicAdd(&g_sums[0], s);
    }
}

__global__ void k_final(const float* __restrict__ log_lambda,
                        const float* __restrict__ log_alpha,
                        float* __restrict__ out, int n)
{
    float data_loss = (float)(g_sums[0] / (double)n);
    float pde_loss  = (float)(g_sums[1] / (double)n);
    float alpha = expf(log_alpha[0]);
    float lam   = expf(log_lambda[0]);
    out[0] = data_loss + lam * pde_loss;
    out[1] = data_loss;
    out[2] = pde_loss;
    out[3] = alpha;
    out[4] = lam;
}

extern "C" void kernel_launch(void* const* d_in, const int* in_sizes, int n_in,
                              void* d_out, int out_size)
{
    const float* x_data     = (const float*)d_in[0];
    const float* y_data     = (const float*)d_in[1];
    const float* x_phys     = (const float*)d_in[2];
    const float* W0 = (const float*)d_in[3];  const float* b0 = (const float*)d_in[4];
    const float* W1 = (const float*)d_in[5];  const float* b1 = (const float*)d_in[6];
    const float* W2 = (const float*)d_in[7];  const float* b2 = (const float*)d_in[8];
    const float* W3 = (const float*)d_in[9];  const float* b3 = (const float*)d_in[10];
    const float* W4 = (const float*)d_in[11]; const float* b4 = (const float*)d_in[12];
    const float* log_lambda = (const float*)d_in[13];
    const float* log_alpha  = (const float*)d_in[14];
    float* out = (float*)d_out;

    int n = in_sizes[0] / 3;

    const int SH_DATA = (HID * BD + HID * HID) * (int)sizeof(float);      // 48 KB
    const int SH_PHYS = (6 * HID * PTS + HID * HID) * (int)sizeof(float); // 208 KB

    cudaFuncSetAttribute(k_data, cudaFuncAttributeMaxDynamicSharedMemorySize, SH_DATA);
    cudaFuncSetAttribute(k_phys, cudaFuncAttributeMaxDynamicSharedMemorySize, SH_PHYS);

    int grid_d = (n + BD - 1) / BD;
    int grid_p = (n + PTS - 1) / PTS;

    k_zero<<<1, 1>>>();
    k_data<<<grid_d, BD, SH_DATA>>>(x_data, y_data, W0, b0, W1, b1, W2, b2,
                                    W3, b3, W4, b4, n);
    k_phys<<<grid_p, BDP, SH_PHYS>>>(x_phys, W0, b0, W1, b1, W2, b2,
                                     W3, b3, W4, b4, log_alpha, n);
    k_final<<<1, 1>>>(log_lambda, log_alpha, out, n);
}

// round 10
// speedup vs baseline: 2.6673x; 1.1284x over previous
#include <cuda_runtime.h>
#include <math.h>

#define HID 64
#define PTS 128      // points per CTA (both a phys point and a data point per pt)
#define BDP 512      // 4 threads per point; each owns 16 output neurons
#define NW  (BDP/32)

__device__ double g_sums[2];   // [0] = sum (pred-y)^2, [1] = sum residual^2

__global__ void k_zero() { g_sums[0] = 0.0; g_sums[1] = 0.0; }

// Fast, branch-free tanh (abs err ~1e-6).
__device__ __forceinline__ float my_tanhf(float z) {
    float zc = fminf(fmaxf(z, -15.f), 15.f);
    float e  = __expf(2.f * zc);
    return 1.f - __fdividef(2.f, e + 1.f);
}

// ---- packed f32x2 helpers (FFMA2 path, sm_100+) ----------------------------
__device__ __forceinline__ unsigned long long dup2(float v) {
    unsigned long long r;
    asm("mov.b64 %0, {%1, %1};" : "=l"(r) : "f"(v));
    return r;
}
__device__ __forceinline__ unsigned long long pack2(float lo, float hi) {
    unsigned long long r;
    asm("mov.b64 %0, {%1, %2};" : "=l"(r) : "f"(lo), "f"(hi));
    return r;
}
__device__ __forceinline__ void ffma2(unsigned long long& a,
                                      unsigned long long x, unsigned long long y) {
    asm("fma.rn.f32x2 %0, %1, %2, %0;" : "+l"(a) : "l"(x), "l"(y));
}
__device__ __forceinline__ float2 unpk(unsigned long long a) {
    float2 f;
    asm("mov.b64 {%0, %1}, %2;" : "=f"(f.x), "=f"(f.y) : "l"(a));
    return f;
}

// Paired matvec over the 16 owned j (8 f32x2 pairs per channel).
// One broadcast weight load serves both channels.
__device__ __forceinline__ void matvec2(const float* __restrict__ stA,
                                        const float* __restrict__ stB,
                                        const float* __restrict__ wsh,
                                        unsigned long long* zA,
                                        unsigned long long* zB,
                                        int pt, int jbase) {
    #pragma unroll 4
    for (int i = 0; i < HID; i++) {
        unsigned long long vA = dup2(stA[i * PTS + pt]);
        unsigned long long vB = dup2(stB[i * PTS + pt]);
        const ulonglong2* wr = (const ulonglong2*)(wsh + i * HID + jbase);
        #pragma unroll
        for (int k = 0; k < 4; k++) {
            ulonglong2 w = wr[k];            // LDS.128 broadcast
            ffma2(zA[2 * k],     vA, w.x);
            ffma2(zA[2 * k + 1], vA, w.y);
            ffma2(zB[2 * k],     vB, w.x);
            ffma2(zB[2 * k + 1], vB, w.y);
        }
    }
}

// ============================================================================
// Fully fused kernel. Channels:
//   0=h(phys) 1=ut 2=ux 3=uy 4=L (Laplacian)  5=hd (data-point value)
// Per layer: pass1=(h,ut), pass2=(ux,uy), pass3=(L,hd). q and t live in
// registers (thread-local across passes by consistent j-ownership).
// Each CTA processes 128 phys points AND 128 data points.
// ============================================================================
__global__ __launch_bounds__(BDP, 1) void k_fused(
    const float* __restrict__ xd,       // x_data
    const float* __restrict__ yd,       // y_data
    const float* __restrict__ xp,       // x_phys
    const float* __restrict__ W0, const float* __restrict__ b0,
    const float* __restrict__ W1, const float* __restrict__ b1,
    const float* __restrict__ W2, const float* __restrict__ b2,
    const float* __restrict__ W3, const float* __restrict__ b3,
    const float* __restrict__ W4, const float* __restrict__ b4,
    const float* __restrict__ log_alpha,
    int n)
{
    extern __shared__ float sh[];
    float* st  = sh;                        // [6][HID][PTS]
    float* wsh = sh + 6 * HID * PTS;        // 64x64 staged weights / scratch
    const int tid   = threadIdx.x;
    const int pt    = tid & (PTS - 1);
    const int quar  = tid >> 7;             // 0..3
    const int jbase = quar << 4;            // 0,16,32,48
    const int p     = blockIdx.x * PTS + pt;
    const bool active = p < n;

    float px0 = 0.f, px1 = 0.f, px2 = 0.f;  // phys point
    float dx0 = 0.f, dx1 = 0.f, dx2 = 0.f;  // data point
    if (active) {
        px0 = xp[3 * p]; px1 = xp[3 * p + 1]; px2 = xp[3 * p + 2];
        dx0 = xd[3 * p]; dx1 = xd[3 * p + 1]; dx2 = xd[3 * p + 2];
    }

    // ---- layer 0: 3 -> 64, own 16 neurons, all 6 channels ----
    #pragma unroll 4
    for (int jj = 0; jj < 16; jj++) {
        int j = jbase + jj;
        float wx = __ldg(W0 + j);
        float wy = __ldg(W0 + HID + j);
        float wt = __ldg(W0 + 2 * HID + j);
        float bj = __ldg(b0 + j);
        float zh = bj + px0 * wx + px1 * wy + px2 * wt;
        float zd = bj + dx0 * wx + dx1 * wy + dx2 * wt;
        float t = my_tanhf(zh);
        float s = 1.f - t * t;
        st[(0 * HID + j) * PTS + pt] = t;
        st[(1 * HID + j) * PTS + pt] = s * wt;                         // ut
        st[(2 * HID + j) * PTS + pt] = s * wx;                         // ux
        st[(3 * HID + j) * PTS + pt] = s * wy;                         // uy
        st[(4 * HID + j) * PTS + pt] = -2.f * t * s * (wx*wx + wy*wy); // Laplacian
        st[(5 * HID + j) * PTS + pt] = my_tanhf(zd);                   // data value
    }

    float t_r[16];   // tanh(z) for own j, current layer (set in epi1)
    float q_r[16];   // zx^2+zy^2 for own j (set in epi2, used in epi3)

    // ---- hidden layers 1..3 ----
    #pragma unroll 1
    for (int l = 0; l < 3; l++) {
        const float* W  = (l == 0) ? W1 : (l == 1) ? W2 : W3;
        const float* bb = (l == 0) ? b1 : (l == 1) ? b2 : b3;

        __syncthreads();   // prev-layer epi writes visible; wsh reads retired
        {
            const float4* src = (const float4*)W;
            float4*       dst = (float4*)wsh;
            #pragma unroll
            for (int k = 0; k < (HID * HID / 4) / BDP; k++)   // 2 float4/thread
                dst[k * BDP + tid] = src[k * BDP + tid];
        }
        __syncthreads();

        unsigned long long zA[8], zB[8];

        // --- pass1: (h, ut). zA = b + h@W ; zB = ut@W ---
        #pragma unroll
        for (int m = 0; m < 8; m++) {
            float2 bv = __ldg((const float2*)bb + (jbase >> 1) + m);
            zA[m] = pack2(bv.x, bv.y);
            zB[m] = 0ull;
        }
        matvec2(st + 0 * HID * PTS, st + 1 * HID * PTS, wsh, zA, zB, pt, jbase);
        __syncthreads();                    // all reads of ch0/ch1 done
        #pragma unroll
        for (int m = 0; m < 8; m++) {
            float2 zh = unpk(zA[m]);
            float2 zt = unpk(zB[m]);
            #pragma unroll
            for (int hh = 0; hh < 2; hh++) {
                int j = jbase + 2 * m + hh;
                float t = my_tanhf(hh ? zh.y : zh.x);
                float s = 1.f - t * t;
                t_r[2 * m + hh] = t;
                st[(0 * HID + j) * PTS + pt] = t;
                st[(1 * HID + j) * PTS + pt] = s * (hh ? zt.y : zt.x);
            }
        }

        // --- pass2: (ux, uy). Epi: q_r = zx^2+zy^2; ux=s*zx; uy=s*zy ---
        #pragma unroll
        for (int m = 0; m < 8; m++) { zA[m] = 0ull; zB[m] = 0ull; }
        matvec2(st + 2 * HID * PTS, st + 3 * HID * PTS, wsh, zA, zB, pt, jbase);
        __syncthreads();                    // all reads of ch2/ch3 done
        #pragma unroll
        for (int m = 0; m < 8; m++) {
            float2 zx = unpk(zA[m]);
            float2 zy = unpk(zB[m]);
            #pragma unroll
            for (int hh = 0; hh < 2; hh++) {
                int j = jbase + 2 * m + hh;
                float zxv = hh ? zx.y : zx.x;
                float zyv = hh ? zy.y : zy.x;
                float t = t_r[2 * m + hh];
                float s = 1.f - t * t;
                st[(2 * HID + j) * PTS + pt] = s * zxv;
                st[(3 * HID + j) * PTS + pt] = s * zyv;
                q_r[2 * m + hh] = zxv * zxv + zyv * zyv;
            }
        }

        // --- pass3: (L, hd). Epi: L=s*zL-2*t*s*q; hd=tanh(zd) ---
        #pragma unroll
        for (int m = 0; m < 8; m++) zA[m] = 0ull;
        #pragma unroll
        for (int m = 0; m < 8; m++) {
            float2 bv = __ldg((const float2*)bb + (jbase >> 1) + m);
            zB[m] = pack2(bv.x, bv.y);      // data channel carries the bias
        }
        matvec2(st + 4 * HID * PTS, st + 5 * HID * PTS, wsh, zA, zB, pt, jbase);
        __syncthreads();                    // all reads of ch4/ch5 done
        #pragma unroll
        for (int m = 0; m < 8; m++) {
            float2 zl = unpk(zA[m]);
            float2 zd = unpk(zB[m]);
            #pragma unroll
            for (int hh = 0; hh < 2; hh++) {
                int j = jbase + 2 * m + hh;
                float zlv = hh ? zl.y : zl.x;
                float t = t_r[2 * m + hh];
                float s = 1.f - t * t;
                st[(4 * HID + j) * PTS + pt] = s * zlv - 2.f * t * s * q_r[2 * m + hh];
                st[(5 * HID + j) * PTS + pt] = my_tanhf(hh ? zd.y : zd.x);
            }
        }
    }

    // ---- output layer: partials over own 16 neurons (all self-written) ----
    float at = 0.f, aL = 0.f, ad = 0.f;
    #pragma unroll 4
    for (int jj = 0; jj < 16; jj++) {
        int j = jbase + jj;
        float w = __ldg(W4 + j);
        at += st[(1 * HID + j) * PTS + pt] * w;
        aL += st[(4 * HID + j) * PTS + pt] * w;
        ad += st[(5 * HID + j) * PTS + pt] * w;
    }
    float alpha = expf(__ldg(log_alpha));
    float rp = at - alpha * aL;             // partial residual (linear in partials)

    // wsh free (post-pass3 barrier passed): combine quarters
    wsh[quar * PTS + pt]            = rp;
    wsh[4 * PTS + quar * PTS + pt]  = ad;
    __syncthreads();

    double lr = 0.0, ld = 0.0;
    if (quar == 0 && active) {
        float r = rp + wsh[PTS + pt] + wsh[2 * PTS + pt] + wsh[3 * PTS + pt];
        lr = (double)r * (double)r;
        float ah = __ldg(b4) + ad + wsh[4 * PTS + PTS + pt]
                 + wsh[4 * PTS + 2 * PTS + pt] + wsh[4 * PTS + 3 * PTS + pt];
        float d = ah - yd[p];
        ld = (double)d * (double)d;
    }

    // block reductions -> atomics (both sums)
    #pragma unroll
    for (int off = 16; off; off >>= 1) {
        lr += __shfl_down_sync(0xffffffffu, lr, off);
        ld += __shfl_down_sync(0xffffffffu, ld, off);
    }
    __syncthreads();
    double* red = (double*)sh;              // 2*NW doubles
    int lane = tid & 31, wid = tid >> 5;
    if (lane == 0) { red[wid] = lr; red[NW + wid] = ld; }
    __syncthreads();
    if (tid == 0) {
        double sr = 0.0, sd = 0.0;
        #pragma unroll
        for (int w = 0; w < NW; w++) { sr += red[w]; sd += red[NW + w]; }
        atomicAdd(&g_sums[1], sr);
        atomicAdd(&g_sums[0], sd);
    }
}

__global__ void k_final(const float* __restrict__ log_lambda,
                        const float* __restrict__ log_alpha,
                        float* __restrict__ out, int n)
{
    float data_loss = (float)(g_sums[0] / (double)n);
    float pde_loss  = (float)(g_sums[1] / (double)n);
    float alpha = expf(log_alpha[0]);
    float lam   = expf(log_lambda[0]);
    out[0] = data_loss + lam * pde_loss;
    out[1] = data_loss;
    out[2] = pde_loss;
    out[3] = alpha;
    out[4] = lam;
}

extern "C" void kernel_launch(void* const* d_in, const int* in_sizes, int n_in,
                              void* d_out, int out_size)
{
    const float* x_data     = (const float*)d_in[0];
    const float* y_data     = (const float*)d_in[1];
    const float* x_phys     = (const float*)d_in[2];
    const float* W0 = (const float*)d_in[3];  const float* b0 = (const float*)d_in[4];
    const float* W1 = (const float*)d_in[5];  const float* b1 = (const float*)d_in[6];
    const float* W2 = (const float*)d_in[7];  const float* b2 = (const float*)d_in[8];
    const float* W3 = (const float*)d_in[9];  const float* b3 = (const float*)d_in[10];
    const float* W4 = (const float*)d_in[11]; const float* b4 = (const float*)d_in[12];
    const float* log_lambda = (const float*)d_in[13];
    const float* log_alpha  = (const float*)d_in[14];
    float* out = (float*)d_out;

    int n = in_sizes[0] / 3;

    const int SH = (6 * HID * PTS + HID * HID) * (int)sizeof(float);  // 208 KB
    cudaFuncSetAttribute(k_fused, cudaFuncAttributeMaxDynamicSharedMemorySize, SH);

    int grid = (n + PTS - 1) / PTS;

    k_zero<<<1, 1>>>();
    k_fused<<<grid, BDP, SH>>>(x_data, y_data, x_phys, W0, b0, W1, b1, W2, b2,
                               W3, b3, W4, b4, log_alpha, n);
    k_final<<<1, 1>>>(log_lambda, log_alpha, out, n);
}

// round 12
// speedup vs baseline: 2.7787x; 1.0418x over previous
#include <cuda_runtime.h>
#include <math.h>

#define HID 64
#define PTS 64       // points per CTA (a phys point AND a data point per pt)
#define BDP 512      // 8 threads per point; each owns 8 output neurons
#define NW  (BDP/32)

__device__ double g_sums[2];   // [0] = sum (pred-y)^2, [1] = sum residual^2

__global__ void k_zero() { g_sums[0] = 0.0; g_sums[1] = 0.0; }

// Fast, branch-free tanh (abs err ~1e-6).
__device__ __forceinline__ float my_tanhf(float z) {
    float zc = fminf(fmaxf(z, -15.f), 15.f);
    float e  = __expf(2.f * zc);
    return 1.f - __fdividef(2.f, e + 1.f);
}

// ---- packed f32x2 helpers (FFMA2 path, sm_100+) ----------------------------
__device__ __forceinline__ unsigned long long dup2(float v) {
    unsigned long long r;
    asm("mov.b64 %0, {%1, %1};" : "=l"(r) : "f"(v));
    return r;
}
__device__ __forceinline__ unsigned long long pack2(float lo, float hi) {
    unsigned long long r;
    asm("mov.b64 %0, {%1, %2};" : "=l"(r) : "f"(lo), "f"(hi));
    return r;
}
__device__ __forceinline__ void ffma2(unsigned long long& a,
                                      unsigned long long x, unsigned long long y) {
    asm("fma.rn.f32x2 %0, %1, %2, %0;" : "+l"(a) : "l"(x), "l"(y));
}
__device__ __forceinline__ float2 unpk(unsigned long long a) {
    float2 f;
    asm("mov.b64 {%0, %1}, %2;" : "=f"(f.x), "=f"(f.y) : "l"(a));
    return f;
}

// Paired matvec over the 8 owned j (4 f32x2 pairs per channel).
// State pair (chA,chB) comes from ONE interleaved float2 buffer: 1 LDS.64/i.
__device__ __forceinline__ void matvec2p(const float2* __restrict__ stP,
                                         const float* __restrict__ wsh,
                                         unsigned long long* zA,
                                         unsigned long long* zB,
                                         int pt, int jbase) {
    #pragma unroll 4
    for (int i = 0; i < HID; i++) {
        float2 v = stP[i * PTS + pt];            // (chA, chB) for this i, point
        unsigned long long vA = dup2(v.x);
        unsigned long long vB = dup2(v.y);
        const ulonglong2* wr = (const ulonglong2*)(wsh + i * HID + jbase);
        #pragma unroll
        for (int k = 0; k < 2; k++) {
            ulonglong2 w = wr[k];                // LDS.128, warp-uniform broadcast
            ffma2(zA[2 * k],     vA, w.x);
            ffma2(zA[2 * k + 1], vA, w.y);
            ffma2(zB[2 * k],     vB, w.x);
            ffma2(zB[2 * k + 1], vB, w.y);
        }
    }
}

// ============================================================================
// Fully fused kernel. Interleaved channel pairs in SMEM:
//   P0 = (h, ut)   P1 = (ux, uy)   P2 = (L, hd)
// 8 threads per point (oct = tid>>6 owns j in [8*oct, 8*oct+8)).
// Per layer: pass0=P0, pass1=P1, pass2=P2; q lives in registers, t re-read
// from the self-written P0 slot (thread-local ownership, no barrier needed).
// 112 KB SMEM/CTA -> 2 CTAs/SM -> 8 warps/SMSP.
// ============================================================================
__global__ __launch_bounds__(BDP, 2) void k_fused(
    const float* __restrict__ xd,       // x_data
    const float* __restrict__ yd,       // y_data
    const float* __restrict__ xp,       // x_phys
    const float* __restrict__ W0, const float* __restrict__ b0,
    const float* __restrict__ W1, const float* __restrict__ b1,
    const float* __restrict__ W2, const float* __restrict__ b2,
    const float* __restrict__ W3, const float* __restrict__ b3,
    const float* __restrict__ W4, const float* __restrict__ b4,
    const float* __restrict__ log_alpha,
    int n)
{
    extern __shared__ float sh[];
    float2* P0 = (float2*)sh;                    // [HID][PTS] pairs
    float2* P1 = P0 + HID * PTS;
    float2* P2 = P1 + HID * PTS;
    float*  wsh = sh + 6 * HID * PTS;            // 64x64 staged weights / scratch
    const int tid   = threadIdx.x;
    const int pt    = tid & (PTS - 1);
    const int oct   = tid >> 6;                  // 0..7
    const int jbase = oct << 3;                  // 0,8,...,56
    const int p     = blockIdx.x * PTS + pt;
    const bool active = p < n;

    float px0 = 0.f, px1 = 0.f, px2 = 0.f;       // phys point
    float dx0 = 0.f, dx1 = 0.f, dx2 = 0.f;       // data point
    if (active) {
        px0 = xp[3 * p]; px1 = xp[3 * p + 1]; px2 = xp[3 * p + 2];
        dx0 = xd[3 * p]; dx1 = xd[3 * p + 1]; dx2 = xd[3 * p + 2];
    }

    // ---- layer 0: 3 -> 64, own 8 neurons, all channels ----
    #pragma unroll 4
    for (int jj = 0; jj < 8; jj++) {
        int j = jbase + jj;
        float wx = __ldg(W0 + j);
        float wy = __ldg(W0 + HID + j);
        float wt = __ldg(W0 + 2 * HID + j);
        float bj = __ldg(b0 + j);
        float zh = bj + px0 * wx + px1 * wy + px2 * wt;
        float zd = bj + dx0 * wx + dx1 * wy + dx2 * wt;
        float t = my_tanhf(zh);
        float s = 1.f - t * t;
        P0[j * PTS + pt] = make_float2(t, s * wt);
        P1[j * PTS + pt] = make_float2(s * wx, s * wy);
        P2[j * PTS + pt] = make_float2(-2.f * t * s * (wx * wx + wy * wy),
                                       my_tanhf(zd));
    }

    float q_r[8];    // zx^2+zy^2 for own j (set in epi1, used in epi2)

    // ---- hidden layers 1..3 ----
    #pragma unroll 1
    for (int l = 0; l < 3; l++) {
        const float* W  = (l == 0) ? W1 : (l == 1) ? W2 : W3;
        const float* bb = (l == 0) ? b1 : (l == 1) ? b2 : b3;

        __syncthreads();   // prev-layer epi writes visible; wsh reads retired
        {
            const float4* src = (const float4*)W;
            float4*       dst = (float4*)wsh;
            #pragma unroll
            for (int k = 0; k < (HID * HID / 4) / BDP; k++)   // 2 float4/thread
                dst[k * BDP + tid] = src[k * BDP + tid];
        }
        __syncthreads();

        unsigned long long zA[4], zB[4];

        // --- pass0: (h, ut). zA = b + h@W ; zB = ut@W ---
        #pragma unroll
        for (int m = 0; m < 4; m++) {
            float2 bv = __ldg((const float2*)bb + (jbase >> 1) + m);
            zA[m] = pack2(bv.x, bv.y);
            zB[m] = 0ull;
        }
        matvec2p(P0, wsh, zA, zB, pt, jbase);
        __syncthreads();                    // all reads of P0 done
        #pragma unroll
        for (int m = 0; m < 4; m++) {
            float2 zh = unpk(zA[m]);
            float2 zt = unpk(zB[m]);
            #pragma unroll
            for (int hh = 0; hh < 2; hh++) {
                int j = jbase + 2 * m + hh;
                float t = my_tanhf(hh ? zh.y : zh.x);
                float s = 1.f - t * t;
                P0[j * PTS + pt] = make_float2(t, s * (hh ? zt.y : zt.x));
            }
        }

        // --- pass1: (ux, uy). Epi: q_r = zx^2+zy^2; write (s*zx, s*zy) ---
        #pragma unroll
        for (int m = 0; m < 4; m++) { zA[m] = 0ull; zB[m] = 0ull; }
        matvec2p(P1, wsh, zA, zB, pt, jbase);
        __syncthreads();                    // all reads of P1 done
        #pragma unroll
        for (int m = 0; m < 4; m++) {
            float2 zx = unpk(zA[m]);
            float2 zy = unpk(zB[m]);
            #pragma unroll
            for (int hh = 0; hh < 2; hh++) {
                int j = jbase + 2 * m + hh;
                float zxv = hh ? zx.y : zx.x;
                float zyv = hh ? zy.y : zy.x;
                float t = P0[j * PTS + pt].x;   // self-written in epi0
                float s = 1.f - t * t;
                P1[j * PTS + pt] = make_float2(s * zxv, s * zyv);
                q_r[2 * m + hh] = zxv * zxv + zyv * zyv;
            }
        }

        // --- pass2: (L, hd). Epi: L=s*zL-2*t*s*q; hd=tanh(zd) ---
        #pragma unroll
        for (int m = 0; m < 4; m++) {
            float2 bv = __ldg((const float2*)bb + (jbase >> 1) + m);
            zA[m] = 0ull;
            zB[m] = pack2(bv.x, bv.y);      // data channel carries the bias
        }
        matvec2p(P2, wsh, zA, zB, pt, jbase);
        __syncthreads();                    // all reads of P2 done
        #pragma unroll
        for (int m = 0; m < 4; m++) {
            float2 zl = unpk(zA[m]);
            float2 zd = unpk(zB[m]);
            #pragma unroll
            for (int hh = 0; hh < 2; hh++) {
                int j = jbase + 2 * m + hh;
                float zlv = hh ? zl.y : zl.x;
                float t = P0[j * PTS + pt].x;
                float s = 1.f - t * t;
                P2[j * PTS + pt] = make_float2(
                    s * zlv - 2.f * t * s * q_r[2 * m + hh],
                    my_tanhf(hh ? zd.y : zd.x));
            }
        }
    }

    // ---- output layer: partials over own 8 neurons (all self-written) ----
    float at = 0.f, aL = 0.f, ad = 0.f;
    #pragma unroll 4
    for (int jj = 0; jj < 8; jj++) {
        int j = jbase + jj;
        float w = __ldg(W4 + j);
        at += P0[j * PTS + pt].y * w;
        float2 v2 = P2[j * PTS + pt];
        aL += v2.x * w;
        ad += v2.y * w;
    }
    float alpha = expf(__ldg(log_alpha));
    float rp = at - alpha * aL;             // partial residual (linear in partials)

    // wsh free (post-pass2 barrier passed): combine the 8 octs per point
    wsh[oct * PTS + pt]            = rp;
    wsh[8 * PTS + oct * PTS + pt]  = ad;
    __syncthreads();

    double lr = 0.0, ld = 0.0;
    if (oct == 0 && active) {
        float r = rp, ah = ad;
        #pragma unroll
        for (int o = 1; o < 8; o++) {
            r  += wsh[o * PTS + pt];
            ah += wsh[8 * PTS + o * PTS + pt];
        }
        lr = (double)r * (double)r;
        ah += __ldg(b4);
        float d = ah - yd[p];
        ld = (double)d * (double)d;
    }

    // block reductions -> atomics (both sums)
    #pragma unroll
    for (int off = 16; off; off >>= 1) {
        lr += __shfl_down_sync(0xffffffffu, lr, off);
        ld += __shfl_down_sync(0xffffffffu, ld, off);
    }
    __syncthreads();
    double* red = (double*)sh;              // 2*NW doubles
    int lane = tid & 31, wid = tid >> 5;
    if (lane == 0) { red[wid] = lr; red[NW + wid] = ld; }
    __syncthreads();
    if (tid == 0) {
        double sr = 0.0, sd = 0.0;
        #pragma unroll
        for (int w = 0; w < NW; w++) { sr += red[w]; sd += red[NW + w]; }
        atomicAdd(&g_sums[1], sr);
        atomicAdd(&g_sums[0], sd);
    }
}

__global__ void k_final(const float* __restrict__ log_lambda,
                        const float* __restrict__ log_alpha,
                        float* __restrict__ out, int n)
{
    float data_loss = (float)(g_sums[0] / (double)n);
    float pde_loss  = (float)(g_sums[1] / (double)n);
    float alpha = expf(log_alpha[0]);
    float lam   = expf(log_lambda[0]);
    out[0] = data_loss + lam * pde_loss;
    out[1] = data_loss;
    out[2] = pde_loss;
    out[3] = alpha;
    out[4] = lam;
}

extern "C" void kernel_launch(void* const* d_in, const int* in_sizes, int n_in,
                              void* d_out, int out_size)
{
    const float* x_data     = (const float*)d_in[0];
    const float* y_data     = (const float*)d_in[1];
    const float* x_phys     = (const float*)d_in[2];
    const float* W0 = (const float*)d_in[3];  const float* b0 = (const float*)d_in[4];
    const float* W1 = (const float*)d_in[5];  const float* b1 = (const float*)d_in[6];
    const float* W2 = (const float*)d_in[7];  const float* b2 = (const float*)d_in[8];
    const float* W3 = (const float*)d_in[9];  const float* b3 = (const float*)d_in[10];
    const float* W4 = (const float*)d_in[11]; const float* b4 = (const float*)d_in[12];
    const float* log_lambda = (const float*)d_in[13];
    const float* log_alpha  = (const float*)d_in[14];
    float* out = (float*)d_out;

    int n = in_sizes[0] / 3;

    // 3 pair-buffers (96 KB) + 64x64 weights (16 KB) = 112 KB -> 2 CTAs/SM
    const int SH = (6 * HID * PTS + HID * HID) * (int)sizeof(float);
    cudaFuncSetAttribute(k_fused, cudaFuncAttributeMaxDynamicSharedMemorySize, SH);

    int grid = (n + PTS - 1) / PTS;

    k_zero<<<1, 1>>>();
    k_fused<<<grid, BDP, SH>>>(x_data, y_data, x_phys, W0, b0, W1, b1, W2, b2,
                               W3, b3, W4, b4, log_alpha, n);
    k_final<<<1, 1>>>(log_lambda, log_alpha, out, n);
}